// round 4
// baseline (speedup 1.0000x reference)
#include <cuda_runtime.h>
#include <cuda_bf16.h>
#include <cstdint>

#define BN 2048   // B*N rows
#define NN 256    // N (neighbors)
#define D  128
#define E  64

// Scratch (device globals: allocation-free rule)
__device__ __align__(16) float g_hW1[BN * E];
__device__ __align__(16) float g_aggmean[BN * D];
__device__ __align__(16) float g_aggmax[BN * D];

__device__ __forceinline__ float tanh_fast(float x) {
    float y;
    asm("tanh.approx.f32 %0, %1;" : "=f"(y) : "f"(x));
    return y;
}

__device__ __forceinline__ uint32_t f2tf32(float f) {
    uint32_t r;
    asm("cvt.rna.tf32.f32 %0, %1;" : "=r"(r) : "f"(f));
    return r;
}

// ---------------------------------------------------------------------------
// K1: hW1 = h @ W1[0:128,:] + b1   (2048 x 64), 8 rows/CTA, grid 256
// ---------------------------------------------------------------------------
__global__ void __launch_bounds__(256) k1_hW1(const float* __restrict__ h,
                                              const float* __restrict__ W1,
                                              const float* __restrict__ b1) {
    __shared__ __align__(16) float s_h[8][128];
    const int tid = threadIdx.x;
    const int r0 = blockIdx.x * 8;
    {
        const int r = tid >> 5, c = tid & 31;
        ((float4*)&s_h[r][0])[c] = ((const float4*)(h + (size_t)(r0 + r) * D))[c];
    }
    __syncthreads();
    const int e  = tid & 63;
    const int rp = (tid >> 6) * 2;   // rows rp, rp+1
    float a0 = 0.f, a1 = 0.f;
#pragma unroll 8
    for (int k = 0; k < 128; k++) {
        const float w = W1[k * E + e];
        a0 += s_h[rp][k] * w;
        a1 += s_h[rp + 1][k] * w;
    }
    const float bb = b1[e];
    g_hW1[(size_t)(r0 + rp) * E + e]     = a0 + bb;
    g_hW1[(size_t)(r0 + rp + 1) * E + e] = a1 + bb;
}

// ---------------------------------------------------------------------------
// K2: per (b,i): compact active j, R = relu(hW1 + ef@W1e) [tf32],
//     logits = R @ W2 via tf32 mma.sync, gate = sigmoid(tanh form),
//     fused masked sum/max/min over j.  One (b,i) row per CTA (R1 config).
// ---------------------------------------------------------------------------
#define K2_SMEM_BYTES ((14336 + 264) * 4)

__global__ void __launch_bounds__(256) k2_main(
    const float* __restrict__ h, const float* __restrict__ ef,
    const unsigned char* __restrict__ adj,
    const float* __restrict__ W1, const float* __restrict__ W2,
    const float* __restrict__ b2) {
    extern __shared__ float sm[];
    float* sW2    = sm;            // 64*136 tf32-rounded
    float* sR     = sm + 8704;     // 64*68  tf32-rounded
    float* s_hW1  = sm + 13056;    // 64
    float* sW1e   = sm + 13120;    // 3*64
    float* s_b2   = sm + 13312;    // 128
    float* s_h    = sm + 13440;    // 128
    float* s_redS = sm + 13568;    // 2*128
    float* s_redMx= sm + 13824;    // 2*128
    float* s_redMn= sm + 14080;    // 2*128
    int*   s_jidx = (int*)(sm + 14336);  // 256
    int*   s_misc = s_jidx + 256;        // 8

    const int bi   = blockIdx.x;
    const int tid  = threadIdx.x;
    const int lane = tid & 31;
    const int warp = tid >> 5;
    const int gid  = lane >> 2;   // 0..7
    const int tg   = lane & 3;    // 0..3
    const int wm   = warp & 1;    // M-group (rows)
    const int wn   = warp >> 1;   // N-group (cols)

    // Stage weights/rows into SMEM (W2 converted to tf32 once per CTA)
    for (int idx = tid; idx < E * D; idx += 256) {
        const int e = idx >> 7, d = idx & 127;
        sW2[e * 136 + d] = __uint_as_float(f2tf32(W2[idx]));
    }
    if (tid < E) s_hW1[tid] = g_hW1[bi * E + tid];
    for (int idx = tid; idx < 3 * E; idx += 256) sW1e[idx] = W1[D * E + idx];
    if (tid < D) { s_b2[tid] = b2[tid]; s_h[tid] = h[bi * D + tid]; }

    // Deterministic compaction of active j (ballot + scan)
    const bool m = adj[(size_t)bi * NN + tid] != 0;
    const unsigned bal = __ballot_sync(0xffffffffu, m);
    if (lane == 0) s_misc[warp] = __popc(bal);
    __syncthreads();
    int base = 0, cnt = 0;
#pragma unroll
    for (int w = 0; w < 8; w++) {
        const int c = s_misc[w];
        if (w < warp) base += c;
        cnt += c;
    }
    if (m) s_jidx[base + __popc(bal & ((1u << lane) - 1u))] = tid;
    __syncthreads();

    float S[8], Mx[8], Mn[8];
#pragma unroll
    for (int i = 0; i < 8; i++) { S[i] = 0.f; Mx[i] = -1e30f; Mn[i] = 1e30f; }

    const int nTiles = (cnt + 63) >> 6;
    const int rrow = tid >> 2;          // 0..63 (R build row)
    const int re0  = (tid & 3) << 4;    // e-chunk base

    for (int t = 0; t < nTiles; t++) {
        if (t) __syncthreads();  // protect sR reuse across tiles
        // ---- Build R tile (64 rows x 64 e), tf32-rounded ----
        float f0 = 0.f, f1 = 0.f, f2v = 0.f;
        const int jg = t * 64 + rrow;
        if (jg < cnt) {
            const float* p = ef + ((size_t)bi * NN + s_jidx[jg]) * 3;
            f0 = p[0]; f1 = p[1]; f2v = p[2];
        }
#pragma unroll
        for (int i = 0; i < 16; i++) {
            const int e = re0 + i;
            float pre = s_hW1[e] + f0 * sW1e[e] + f1 * sW1e[64 + e] + f2v * sW1e[128 + e];
            pre = fmaxf(pre, 0.f);
            sR[rrow * 68 + e] = __uint_as_float(f2tf32(pre));
        }
        __syncthreads();

        // ---- 64x128 logits tile: warp = 32 rows x 32 cols, K=64 (8 x k8) ----
        float c[2][4][4];
#pragma unroll
        for (int mt = 0; mt < 2; mt++)
#pragma unroll
            for (int nt = 0; nt < 4; nt++)
#pragma unroll
                for (int q = 0; q < 4; q++) c[mt][nt][q] = 0.f;

#pragma unroll
        for (int kc = 0; kc < 8; kc++) {
            const int k = kc * 8;
            uint32_t a[2][4], b[4][2];
#pragma unroll
            for (int mt = 0; mt < 2; mt++) {
                const int row = wm * 32 + mt * 16 + gid;
                const float* pr = sR + row * 68 + k + tg;
                a[mt][0] = __float_as_uint(pr[0]);
                a[mt][1] = __float_as_uint(pr[8 * 68]);
                a[mt][2] = __float_as_uint(pr[4]);
                a[mt][3] = __float_as_uint(pr[8 * 68 + 4]);
            }
#pragma unroll
            for (int nt = 0; nt < 4; nt++) {
                const int col = wn * 32 + nt * 8 + gid;
                const float* pb = sW2 + (k + tg) * 136 + col;
                b[nt][0] = __float_as_uint(pb[0]);
                b[nt][1] = __float_as_uint(pb[4 * 136]);
            }
#pragma unroll
            for (int mt = 0; mt < 2; mt++)
#pragma unroll
                for (int nt = 0; nt < 4; nt++) {
                    asm("mma.sync.aligned.m16n8k8.row.col.f32.tf32.tf32.f32 "
                        "{%0,%1,%2,%3}, {%4,%5,%6,%7}, {%8,%9}, {%0,%1,%2,%3};\n"
                        : "+f"(c[mt][nt][0]), "+f"(c[mt][nt][1]),
                          "+f"(c[mt][nt][2]), "+f"(c[mt][nt][3])
                        : "r"(a[mt][0]), "r"(a[mt][1]), "r"(a[mt][2]), "r"(a[mt][3]),
                          "r"(b[nt][0]), "r"(b[nt][1]));
                }
        }

        // ---- Epilogue: bias + sigmoid(tanh) + masked sum/max/min ----
#pragma unroll
        for (int mt = 0; mt < 2; mt++)
#pragma unroll
            for (int q = 0; q < 4; q++) {
                const int rloc = wm * 32 + mt * 16 + gid + ((q >> 1) << 3);
                const bool v = (t * 64 + rloc) < cnt;
#pragma unroll
                for (int nt = 0; nt < 4; nt++) {
                    const int d = wn * 32 + nt * 8 + 2 * tg + (q & 1);
                    const float logit = c[mt][nt][q] + s_b2[d];
                    const float g = fmaf(0.5f, tanh_fast(0.5f * logit), 0.5f);
                    if (v) {
                        const int si = nt * 2 + (q & 1);
                        S[si] += g;
                        Mx[si] = fmaxf(Mx[si], g);
                        Mn[si] = fminf(Mn[si], g);
                    }
                }
            }
    }

    // ---- Reduce across the 8 lanes sharing each d ----
#pragma unroll
    for (int i = 0; i < 8; i++) {
#pragma unroll
        for (int off = 4; off < 32; off <<= 1) {
            S[i]  += __shfl_xor_sync(0xffffffffu, S[i], off);
            Mx[i]  = fmaxf(Mx[i], __shfl_xor_sync(0xffffffffu, Mx[i], off));
            Mn[i]  = fminf(Mn[i], __shfl_xor_sync(0xffffffffu, Mn[i], off));
        }
    }
    if (lane < 4) {
#pragma unroll
        for (int nt = 0; nt < 4; nt++)
#pragma unroll
            for (int q = 0; q < 2; q++) {
                const int d = wn * 32 + nt * 8 + 2 * lane + q;
                const int si = nt * 2 + q;
                s_redS [wm * 128 + d] = S[si];
                s_redMx[wm * 128 + d] = Mx[si];
                s_redMn[wm * 128 + d] = Mn[si];
            }
    }
    __syncthreads();
    if (tid < D) {
        const float St  = s_redS[tid]  + s_redS[128 + tid];
        const float Mxt = fmaxf(s_redMx[tid], s_redMx[128 + tid]);
        const float Mnt = fminf(s_redMn[tid], s_redMn[128 + tid]);
        const float hv  = s_h[tid];
        const float cl  = (cnt > 0) ? (float)cnt : 1.f;
        g_aggmean[bi * D + tid] = St * hv / cl;
        float amax = 0.f;
        if (cnt > 0) amax = (hv >= 0.f) ? hv * Mxt : hv * Mnt;
        g_aggmax[bi * D + tid] = amax;
    }
}

// ---------------------------------------------------------------------------
// K3: upd = relu([h, agg_mean, agg_max] @ U1 + b3) @ U2 + b4
//     out = LayerNorm(h + upd) * gamma + beta
// TR=8 rows/CTA, grid=256.  Packed fp32x2 FMA (FFMA2) + 8x unrolled k-loop
// with register double-buffered weight prefetch.  Exact fp32 numerics.
// ---------------------------------------------------------------------------
#define TR 8
__global__ void __launch_bounds__(256) k3_upd(
    const float* __restrict__ h,
    const float* __restrict__ U1, const float* __restrict__ b3,
    const float* __restrict__ U2, const float* __restrict__ b4,
    const float* __restrict__ gamma, const float* __restrict__ beta,
    float* __restrict__ out) {
    __shared__ __align__(16) float s_inT[384][12];   // [k][row], pad 12
    __shared__ __align__(16) float s_midT[128][12];  // [k][row]
    __shared__ float s_x[TR][129];
    const int tid = threadIdx.x;
    const int r0 = blockIdx.x * TR;

    // Transposed staging
    {
        const int r = tid >> 5, c = tid & 31;
        const int k = c * 4;
        const float4 va = ((const float4*)(h + (size_t)(r0 + r) * D))[c];
        const float4 vb = ((const float4*)(g_aggmean + (size_t)(r0 + r) * D))[c];
        const float4 vc = ((const float4*)(g_aggmax + (size_t)(r0 + r) * D))[c];
        s_inT[k + 0][r] = va.x; s_inT[k + 1][r] = va.y;
        s_inT[k + 2][r] = va.z; s_inT[k + 3][r] = va.w;
        s_inT[128 + k + 0][r] = vb.x; s_inT[128 + k + 1][r] = vb.y;
        s_inT[128 + k + 2][r] = vb.z; s_inT[128 + k + 3][r] = vb.w;
        s_inT[256 + k + 0][r] = vc.x; s_inT[256 + k + 1][r] = vc.y;
        s_inT[256 + k + 2][r] = vc.z; s_inT[256 + k + 3][r] = vc.w;
    }
    __syncthreads();

    const int e  = tid & 127;       // output column
    const int rb = (tid >> 7) * 4;  // row base (0 or 4)

    unsigned long long a01 = 0ull, a23 = 0ull;   // packed f32x2 accumulators
    float w[8];
#pragma unroll
    for (int i = 0; i < 8; i++) w[i] = U1[i * D + e];
    for (int k = 0; k < 384; k += 8) {
        float wn[8];
        if (k + 8 < 384) {
#pragma unroll
            for (int i = 0; i < 8; i++) wn[i] = U1[(k + 8 + i) * D + e];
        }
#pragma unroll
        for (int i = 0; i < 8; i++) {
            const ulonglong2 v = *(const ulonglong2*)&s_inT[k + i][rb];
            unsigned long long wp;
            asm("mov.b64 %0, {%1, %1};" : "=l"(wp) : "r"(__float_as_uint(w[i])));
            asm("fma.rn.f32x2 %0, %1, %2, %0;" : "+l"(a01) : "l"(v.x), "l"(wp));
            asm("fma.rn.f32x2 %0, %1, %2, %0;" : "+l"(a23) : "l"(v.y), "l"(wp));
        }
#pragma unroll
        for (int i = 0; i < 8; i++) w[i] = wn[i];
    }
    {
        const float bb = b3[e];
        uint32_t l0, h0, l1, h1;
        asm("mov.b64 {%0, %1}, %2;" : "=r"(l0), "=r"(h0) : "l"(a01));
        asm("mov.b64 {%0, %1}, %2;" : "=r"(l1), "=r"(h1) : "l"(a23));
        float4 mv;
        mv.x = fmaxf(__uint_as_float(l0) + bb, 0.f);
        mv.y = fmaxf(__uint_as_float(h0) + bb, 0.f);
        mv.z = fmaxf(__uint_as_float(l1) + bb, 0.f);
        mv.w = fmaxf(__uint_as_float(h1) + bb, 0.f);
        *(float4*)&s_midT[e][rb] = mv;
    }
    __syncthreads();

    a01 = 0ull; a23 = 0ull;
#pragma unroll
    for (int i = 0; i < 8; i++) w[i] = U2[i * D + e];
    for (int k = 0; k < 128; k += 8) {
        float wn[8];
        if (k + 8 < 128) {
#pragma unroll
            for (int i = 0; i < 8; i++) wn[i] = U2[(k + 8 + i) * D + e];
        }
#pragma unroll
        for (int i = 0; i < 8; i++) {
            const ulonglong2 v = *(const ulonglong2*)&s_midT[k + i][rb];
            unsigned long long wp;
            asm("mov.b64 %0, {%1, %1};" : "=l"(wp) : "r"(__float_as_uint(w[i])));
            asm("fma.rn.f32x2 %0, %1, %2, %0;" : "+l"(a01) : "l"(v.x), "l"(wp));
            asm("fma.rn.f32x2 %0, %1, %2, %0;" : "+l"(a23) : "l"(v.y), "l"(wp));
        }
#pragma unroll
        for (int i = 0; i < 8; i++) w[i] = wn[i];
    }
    {
        const float b4v = b4[e];
        uint32_t l0, h0, l1, h1;
        asm("mov.b64 {%0, %1}, %2;" : "=r"(l0), "=r"(h0) : "l"(a01));
        asm("mov.b64 {%0, %1}, %2;" : "=r"(l1), "=r"(h1) : "l"(a23));
        // h[row][e] lives at s_inT[e][row] (e < 128 is the h segment)
        s_x[rb + 0][e] = s_inT[e][rb + 0] + __uint_as_float(l0) + b4v;
        s_x[rb + 1][e] = s_inT[e][rb + 1] + __uint_as_float(h0) + b4v;
        s_x[rb + 2][e] = s_inT[e][rb + 2] + __uint_as_float(l1) + b4v;
        s_x[rb + 3][e] = s_inT[e][rb + 3] + __uint_as_float(h1) + b4v;
    }
    __syncthreads();

    // LayerNorm: 8 warps, one row each
    const int warp = tid >> 5, lane = tid & 31;
    float s = 0.f, s2 = 0.f, v[4];
#pragma unroll
    for (int i = 0; i < 4; i++) {
        v[i] = s_x[warp][lane + i * 32];
        s += v[i]; s2 += v[i] * v[i];
    }
#pragma unroll
    for (int off = 1; off < 32; off <<= 1) {
        s  += __shfl_xor_sync(0xffffffffu, s, off);
        s2 += __shfl_xor_sync(0xffffffffu, s2, off);
    }
    const float mu  = s * (1.f / 128.f);
    const float var = s2 * (1.f / 128.f) - mu * mu;
    const float inv = rsqrtf(var + 1e-5f);
#pragma unroll
    for (int i = 0; i < 4; i++) {
        const int d = lane + i * 32;
        out[(size_t)(r0 + warp) * D + d] = (v[i] - mu) * inv * gamma[d] + beta[d];
    }
}

// ---------------------------------------------------------------------------
extern "C" void kernel_launch(void* const* d_in, const int* in_sizes, int n_in,
                              void* d_out, int out_size) {
    const float* h    = (const float*)d_in[0];
    const float* ef   = (const float*)d_in[1];
    const unsigned char* adj = (const unsigned char*)d_in[2];
    const float* W1   = (const float*)d_in[3];
    const float* b1   = (const float*)d_in[4];
    const float* W2   = (const float*)d_in[5];
    const float* b2   = (const float*)d_in[6];
    const float* U1   = (const float*)d_in[7];
    const float* b3   = (const float*)d_in[8];
    const float* U2   = (const float*)d_in[9];
    const float* b4   = (const float*)d_in[10];
    const float* gamma= (const float*)d_in[11];
    const float* beta = (const float*)d_in[12];
    float* out = (float*)d_out;

    cudaFuncSetAttribute(k2_main, cudaFuncAttributeMaxDynamicSharedMemorySize,
                         K2_SMEM_BYTES);

    k1_hW1<<<BN / 8, 256>>>(h, W1, b1);
    k2_main<<<BN, 256, K2_SMEM_BYTES>>>(h, ef, adj, W1, W2, b2);
    k3_upd<<<BN / TR, 256>>>(h, U1, b3, U2, b4, gamma, beta, out);
}